// round 3
// baseline (speedup 1.0000x reference)
#include <cuda_runtime.h>
#include <math.h>

#define WRANKS 4
#define NUM_HEADS 32
#define HEAD_SIZE 128
#define GKV 8              // kv heads
#define QPG 4              // query heads per kv head
#define BLOCK_SIZE 16
#define NUM_BLOCKS 1024
#define MAX_BLOCKS 32
#define MAX_CTX 512
#define NSEQ 32
#define ATT_SCALE 0.08838834764831845f  // 1/sqrt(128)

__global__ __launch_bounds__(256, 4)
void dpa_kernel(const float* __restrict__ query,
                const float* __restrict__ key_cache,
                const float* __restrict__ value_cache,
                const int*   __restrict__ block_tables,
                const int*   __restrict__ context_lens,
                float*       __restrict__ out)
{
    __shared__ float logits[QPG][MAX_CTX];   // 8 KB; reused as final reduction buffer
    __shared__ int   bt_s[MAX_BLOCKS];
    __shared__ float m_s[QPG], esum_s[QPG];

    const int sg   = blockIdx.x;           // 0..255
    const int s    = sg >> 3;              // seq
    const int g    = sg & 7;               // kv head
    const int tid  = threadIdx.x;
    const int lane = tid & 31;
    const int warp = tid >> 5;

    // Per-lane Q fragments: qfrag[h] = q[s, g*4+h, lane*4 .. lane*4+3]
    float4 qfrag[QPG];
    const float* qbase = query + (size_t)s * (NUM_HEADS * HEAD_SIZE)
                               + (size_t)g * (QPG * HEAD_SIZE) + lane * 4;
    #pragma unroll
    for (int h = 0; h < QPG; h++)
        qfrag[h] = *(const float4*)(qbase + h * HEAD_SIZE);

    // Running cross-rank merge state (den/M tracked redundantly per thread)
    float M[QPG], den[QPG];
    #pragma unroll
    for (int h = 0; h < QPG; h++) { M[h] = -1e30f; den[h] = 0.0f; }

    // PV numerator: thread owns float2 of d, processes tokens t % 4 == quarter
    const int d2      = tid & 63;   // float2 index within head dim
    const int quarter = tid >> 6;   // 0..3
    float2 num[QPG];
    #pragma unroll
    for (int h = 0; h < QPG; h++) { num[h].x = 0.0f; num[h].y = 0.0f; }

    const size_t rank_stride = (size_t)NUM_BLOCKS * GKV * BLOCK_SIZE * HEAD_SIZE;

    for (int w = 0; w < WRANKS; w++) {
        __syncthreads();  // previous rank's PV done with logits buffer
        const int ctx = context_lens[w * NSEQ + s];
        if (tid < MAX_BLOCKS)
            bt_s[tid] = block_tables[((size_t)w * NSEQ + s) * MAX_BLOCKS + tid];
        __syncthreads();

        // ---- QK logits: warp-per-token -------------------------------------
        const float* kc = key_cache + (size_t)w * rank_stride
                        + (size_t)g * (BLOCK_SIZE * HEAD_SIZE);
        for (int t = warp; t < ctx; t += 8) {
            const int pb = bt_s[t >> 4];
            const float* krow = kc + (size_t)pb * (GKV * BLOCK_SIZE * HEAD_SIZE)
                                   + (size_t)(t & 15) * HEAD_SIZE;
            const float4 k4 = *(const float4*)(krow + lane * 4);
            float part[QPG];
            #pragma unroll
            for (int h = 0; h < QPG; h++) {
                float p = k4.x * qfrag[h].x;
                p = fmaf(k4.y, qfrag[h].y, p);
                p = fmaf(k4.z, qfrag[h].z, p);
                p = fmaf(k4.w, qfrag[h].w, p);
                part[h] = p;
            }
            #pragma unroll
            for (int off = 16; off; off >>= 1) {
                #pragma unroll
                for (int h = 0; h < QPG; h++)
                    part[h] += __shfl_xor_sync(0xFFFFFFFFu, part[h], off);
            }
            if (lane == 0) {
                #pragma unroll
                for (int h = 0; h < QPG; h++)
                    logits[h][t] = part[h] * ATT_SCALE;
            }
        }
        __syncthreads();

        // ---- per-head softmax (warp h handles head h), p stored in-place ---
        if (warp < QPG) {
            const int h = warp;
            float mx = -1e30f;
            for (int t = lane; t < ctx; t += 32)
                mx = fmaxf(mx, logits[h][t]);
            #pragma unroll
            for (int off = 16; off; off >>= 1)
                mx = fmaxf(mx, __shfl_xor_sync(0xFFFFFFFFu, mx, off));
            float sum = 0.0f;
            for (int t = lane; t < ctx; t += 32) {
                const float p = __expf(logits[h][t] - mx);
                logits[h][t] = p;
                sum += p;
            }
            #pragma unroll
            for (int off = 16; off; off >>= 1)
                sum += __shfl_xor_sync(0xFFFFFFFFu, sum, off);
            if (lane == 0) { m_s[h] = mx; esum_s[h] = sum; }
        }
        __syncthreads();

        // ---- PV accumulate: each V element read exactly once ---------------
        const float* vc = value_cache + (size_t)w * rank_stride
                        + (size_t)g * (BLOCK_SIZE * HEAD_SIZE) + d2 * 2;
        float2 pv[QPG];
        #pragma unroll
        for (int h = 0; h < QPG; h++) { pv[h].x = 0.0f; pv[h].y = 0.0f; }
        for (int t = quarter; t < ctx; t += 4) {
            const int pb = bt_s[t >> 4];
            const float2 v2 = *(const float2*)(vc
                + (size_t)pb * (GKV * BLOCK_SIZE * HEAD_SIZE)
                + (size_t)(t & 15) * HEAD_SIZE);
            #pragma unroll
            for (int h = 0; h < QPG; h++) {
                const float p = logits[h][t];
                pv[h].x = fmaf(p, v2.x, pv[h].x);
                pv[h].y = fmaf(p, v2.y, pv[h].y);
            }
        }

        // ---- fold this rank into running LSE merge -------------------------
        #pragma unroll
        for (int h = 0; h < QPG; h++) {
            const float mr = m_s[h], er = esum_s[h];
            const float newM = fmaxf(M[h], mr);
            const float so = __expf(M[h] - newM);
            const float sr = __expf(mr   - newM);
            num[h].x = num[h].x * so + pv[h].x * sr;
            num[h].y = num[h].y * so + pv[h].y * sr;
            den[h]   = den[h]   * so + er      * sr;
            M[h]     = newM;
        }
    }

    // ---- cross-quarter reduction in smem, then write -----------------------
    __syncthreads();
    float* red = &logits[0][0];   // 2048 floats = [quarter][h][d]
    #pragma unroll
    for (int h = 0; h < QPG; h++) {
        red[quarter * 512 + h * 128 + d2 * 2]     = num[h].x;
        red[quarter * 512 + h * 128 + d2 * 2 + 1] = num[h].y;
    }
    __syncthreads();

    const int d  = tid & 127;
    const int h0 = tid >> 7;       // thread covers heads h0 and h0+2
    #pragma unroll
    for (int j = 0; j < 2; j++) {
        const int h = h0 + 2 * j;
        const float v = red[h * 128 + d] + red[512 + h * 128 + d]
                      + red[1024 + h * 128 + d] + red[1536 + h * 128 + d];
        out[(size_t)sg * (QPG * HEAD_SIZE) + h * HEAD_SIZE + d] = v / den[h];
    }
}

extern "C" void kernel_launch(void* const* d_in, const int* in_sizes, int n_in,
                              void* d_out, int out_size)
{
    const float* query        = (const float*)d_in[0];
    const float* key_cache    = (const float*)d_in[1];
    const float* value_cache  = (const float*)d_in[2];
    const int*   block_tables = (const int*)d_in[3];
    const int*   context_lens = (const int*)d_in[4];
    float*       out          = (float*)d_out;

    dpa_kernel<<<NSEQ * GKV, 256>>>(query, key_cache, value_cache,
                                    block_tables, context_lens, out);
}

// round 4
// speedup vs baseline: 2.8106x; 2.8106x over previous
#include <cuda_runtime.h>
#include <math.h>

#define WRANKS 4
#define NUM_HEADS 32
#define HEAD_SIZE 128
#define GKV 8              // kv heads
#define QPG 4              // query heads per kv head
#define BLOCK_SIZE 16
#define NUM_BLOCKS 1024
#define MAX_BLOCKS 32
#define MAX_CTX 512
#define NSEQ 32
#define NCHUNK 2
#define CHUNK 256
#define NPART (WRANKS * NSEQ * GKV * NCHUNK)   // 2048 partials
#define ATT_SCALE 0.08838834764831845f         // 1/sqrt(128)

// Partial-result scratch (4 MB + 32 KB) — __device__ globals per alloc rules.
__device__ float g_num[NPART][QPG][HEAD_SIZE];
__device__ float g_m[NPART][QPG];
__device__ float g_e[NPART][QPG];

// ---------------------------------------------------------------------------
// Kernel A: per-(seq, kv-group, rank, chunk) partial attention.
// grid = (NSEQ*GKV, WRANKS, NCHUNK), block = 256
// ---------------------------------------------------------------------------
__global__ __launch_bounds__(256, 4)
void dpa_partial(const float* __restrict__ query,
                 const float* __restrict__ key_cache,
                 const float* __restrict__ value_cache,
                 const int*   __restrict__ block_tables,
                 const int*   __restrict__ context_lens)
{
    __shared__ float smem[QPG * CHUNK * 2];  // 8 KB: logits (first 4 KB), reused as red buffer
    __shared__ int   bt_s[MAX_BLOCKS];
    __shared__ float m_s[QPG], e_s[QPG];

    const int sg   = blockIdx.x;          // 0..255
    const int s    = sg >> 3;
    const int g    = sg & 7;
    const int w    = blockIdx.y;
    const int c    = blockIdx.z;
    const int tid  = threadIdx.x;
    const int lane = tid & 31;
    const int warp = tid >> 5;

    const int P = ((w * NSEQ + s) * GKV + g) * NCHUNK + c;

    const int ctx = context_lens[w * NSEQ + s];
    const int t0  = c * CHUNK;
    const int t1  = min(ctx, t0 + CHUNK);
    const int n   = t1 - t0;

    if (n <= 0) {
        // Empty partial: zero contribution, m = -inf so reduce weight = 0.
        float* np = &g_num[P][0][0];
        for (int i = tid; i < QPG * HEAD_SIZE; i += 256) np[i] = 0.0f;
        if (tid < QPG) { g_m[P][tid] = -1e30f; g_e[P][tid] = 0.0f; }
        return;
    }

    if (tid < MAX_BLOCKS)
        bt_s[tid] = block_tables[((size_t)w * NSEQ + s) * MAX_BLOCKS + tid];

    // Q fragments, pre-scaled: qf[h] = q[s, g*4+h, lane*4..lane*4+3] * scale
    float4 qf[QPG];
    const float* qb = query + (size_t)s * (NUM_HEADS * HEAD_SIZE)
                            + (size_t)g * (QPG * HEAD_SIZE) + lane * 4;
    #pragma unroll
    for (int h = 0; h < QPG; h++) {
        float4 q4 = *(const float4*)(qb + h * HEAD_SIZE);
        q4.x *= ATT_SCALE; q4.y *= ATT_SCALE; q4.z *= ATT_SCALE; q4.w *= ATT_SCALE;
        qf[h] = q4;
    }
    __syncthreads();

    float* logits = smem;  // [QPG][CHUNK], row stride CHUNK

    const size_t rank_stride = (size_t)NUM_BLOCKS * GKV * BLOCK_SIZE * HEAD_SIZE;
    const size_t page_stride = (size_t)GKV * BLOCK_SIZE * HEAD_SIZE;

    // ---- QK: warp-per-token, 2 tokens in flight per warp-iter --------------
    const float* kc = key_cache + (size_t)w * rank_stride
                    + (size_t)g * (BLOCK_SIZE * HEAD_SIZE);
    for (int ta = t0 + warp; ta < t1; ta += 16) {
        const int tb = ta + 8;
        const bool hasb = (tb < t1);
        const float* ka = kc + (size_t)bt_s[ta >> 4] * page_stride
                             + (size_t)(ta & 15) * HEAD_SIZE;
        const float4 k4a = *(const float4*)(ka + lane * 4);
        float4 k4b = make_float4(0.f, 0.f, 0.f, 0.f);
        if (hasb) {
            const float* kb = kc + (size_t)bt_s[tb >> 4] * page_stride
                                 + (size_t)(tb & 15) * HEAD_SIZE;
            k4b = *(const float4*)(kb + lane * 4);
        }
        float pa[QPG], pb[QPG];
        #pragma unroll
        for (int h = 0; h < QPG; h++) {
            float x = k4a.x * qf[h].x;
            x = fmaf(k4a.y, qf[h].y, x);
            x = fmaf(k4a.z, qf[h].z, x);
            x = fmaf(k4a.w, qf[h].w, x);
            pa[h] = x;
            float y = k4b.x * qf[h].x;
            y = fmaf(k4b.y, qf[h].y, y);
            y = fmaf(k4b.z, qf[h].z, y);
            y = fmaf(k4b.w, qf[h].w, y);
            pb[h] = y;
        }
        #pragma unroll
        for (int off = 16; off; off >>= 1) {
            #pragma unroll
            for (int h = 0; h < QPG; h++) {
                pa[h] += __shfl_xor_sync(0xFFFFFFFFu, pa[h], off);
                pb[h] += __shfl_xor_sync(0xFFFFFFFFu, pb[h], off);
            }
        }
        if (lane == 0) {
            #pragma unroll
            for (int h = 0; h < QPG; h++) {
                logits[h * CHUNK + (ta - t0)] = pa[h];
                if (hasb) logits[h * CHUNK + (tb - t0)] = pb[h];
            }
        }
    }
    __syncthreads();

    // ---- per-head softmax (warp h handles head h), p stored in-place -------
    if (warp < QPG) {
        const int h = warp;
        float mx = -1e30f;
        for (int t = lane; t < n; t += 32)
            mx = fmaxf(mx, logits[h * CHUNK + t]);
        #pragma unroll
        for (int off = 16; off; off >>= 1)
            mx = fmaxf(mx, __shfl_xor_sync(0xFFFFFFFFu, mx, off));
        float sum = 0.0f;
        for (int t = lane; t < n; t += 32) {
            const float p = __expf(logits[h * CHUNK + t] - mx);
            logits[h * CHUNK + t] = p;
            sum += p;
        }
        #pragma unroll
        for (int off = 16; off; off >>= 1)
            sum += __shfl_xor_sync(0xFFFFFFFFu, sum, off);
        if (lane == 0) { m_s[h] = mx; e_s[h] = sum; }
    }
    __syncthreads();

    // ---- PV: per 16-token page, 4 independent V loads per thread -----------
    const int d2      = tid & 63;    // float2 index within head dim
    const int quarter = tid >> 6;    // 0..3
    const float* vc = value_cache + (size_t)w * rank_stride
                    + (size_t)g * (BLOCK_SIZE * HEAD_SIZE) + d2 * 2;
    float2 pv[QPG];
    #pragma unroll
    for (int h = 0; h < QPG; h++) { pv[h].x = 0.0f; pv[h].y = 0.0f; }

    for (int tb = t0; tb < t1; tb += 16) {   // tb always 16-aligned (t0 % 256 == 0)
        const size_t vbase = (size_t)bt_s[tb >> 4] * page_stride;
        #pragma unroll
        for (int j = 0; j < 4; j++) {
            const int t = tb + quarter + 4 * j;
            if (t < t1) {
                const float2 v2 = *(const float2*)(vc + vbase
                    + (size_t)(quarter + 4 * j) * HEAD_SIZE);
                #pragma unroll
                for (int h = 0; h < QPG; h++) {
                    const float p = logits[h * CHUNK + (t - t0)];
                    pv[h].x = fmaf(p, v2.x, pv[h].x);
                    pv[h].y = fmaf(p, v2.y, pv[h].y);
                }
            }
        }
    }

    // ---- cross-quarter reduction, write partials ---------------------------
    __syncthreads();
    float* red = smem;   // 2048 floats: [quarter][h][d]
    #pragma unroll
    for (int h = 0; h < QPG; h++) {
        red[quarter * 512 + h * 128 + d2 * 2]     = pv[h].x;
        red[quarter * 512 + h * 128 + d2 * 2 + 1] = pv[h].y;
    }
    __syncthreads();

    const int d  = tid & 127;
    const int h0 = tid >> 7;
    #pragma unroll
    for (int j = 0; j < 2; j++) {
        const int h = h0 + 2 * j;
        g_num[P][h][d] = red[h * 128 + d] + red[512 + h * 128 + d]
                       + red[1024 + h * 128 + d] + red[1536 + h * 128 + d];
    }
    if (tid < QPG) { g_m[P][tid] = m_s[tid]; g_e[P][tid] = e_s[tid]; }
}

// ---------------------------------------------------------------------------
// Kernel B: cross-(rank, chunk) LSE merge. grid = 256, block = 128 (one per d)
// ---------------------------------------------------------------------------
__global__ __launch_bounds__(128)
void dpa_reduce(float* __restrict__ out)
{
    __shared__ float sm[WRANKS * NCHUNK][QPG];
    __shared__ float se[WRANKS * NCHUNK][QPG];

    const int sg = blockIdx.x;
    const int s = sg >> 3, g = sg & 7;
    const int tid = threadIdx.x;   // d

    if (tid < WRANKS * NCHUNK * QPG) {
        const int p = tid >> 2, h = tid & 3;
        const int w = p >> 1, c = p & 1;
        const int P = ((w * NSEQ + s) * GKV + g) * NCHUNK + c;
        sm[p][h] = g_m[P][h];
        se[p][h] = g_e[P][h];
    }
    __syncthreads();

    #pragma unroll
    for (int h = 0; h < QPG; h++) {
        float gmax = -1e30f;
        #pragma unroll
        for (int p = 0; p < WRANKS * NCHUNK; p++)
            gmax = fmaxf(gmax, sm[p][h]);
        float den = 0.0f, val = 0.0f;
        #pragma unroll
        for (int p = 0; p < WRANKS * NCHUNK; p++) {
            const float wgt = __expf(sm[p][h] - gmax);
            const int w = p >> 1, c = p & 1;
            const int P = ((w * NSEQ + s) * GKV + g) * NCHUNK + c;
            den = fmaf(se[p][h], wgt, den);
            val = fmaf(g_num[P][h][tid], wgt, val);
        }
        out[(size_t)sg * (QPG * HEAD_SIZE) + h * HEAD_SIZE + tid] = val / den;
    }
}

extern "C" void kernel_launch(void* const* d_in, const int* in_sizes, int n_in,
                              void* d_out, int out_size)
{
    const float* query        = (const float*)d_in[0];
    const float* key_cache    = (const float*)d_in[1];
    const float* value_cache  = (const float*)d_in[2];
    const int*   block_tables = (const int*)d_in[3];
    const int*   context_lens = (const int*)d_in[4];
    float*       out          = (float*)d_out;

    dim3 gridA(NSEQ * GKV, WRANKS, NCHUNK);
    dpa_partial<<<gridA, 256>>>(query, key_cache, value_cache,
                                block_tables, context_lens);
    dpa_reduce<<<NSEQ * GKV, 128>>>(out);
}